// round 8
// baseline (speedup 1.0000x reference)
#include <cuda_runtime.h>
#include <cuda_bf16.h>
#include <cstdint>

// Problem constants
#define B_    2048
#define F_    512
#define H_    64
#define K_    8
#define D_    128
#define ASR_  128
#define MM_   768
#define OUT_  256
#define ZPRE_ (ASR_ + MM_)          // 896
#define ZK_   (ZPRE_ + F_ * K_)     // 4992
#define PROJ_IN_ (ASR_ + MM_ + F_ * D_)   // 66432
#define SPLITK 4
#define KSPLIT (ZK_ / SPLITK)       // 1248
#define ITERS  (KSPLIT / 16)        // 78

typedef unsigned long long ull;
typedef uint32_t u32;

// ---------- packed f32x2 helpers ----------
__device__ __forceinline__ ull pack2(float lo, float hi) {
    ull r; asm("mov.b64 %0, {%1, %2};" : "=l"(r) : "f"(lo), "f"(hi)); return r;
}
__device__ __forceinline__ void unpack2(ull v, float& lo, float& hi) {
    asm("mov.b64 {%0, %1}, %2;" : "=f"(lo), "=f"(hi) : "l"(v));
}
__device__ __forceinline__ void ffma2(ull& c, ull a, ull b) {
    asm("fma.rn.f32x2 %0, %1, %2, %0;" : "+l"(c) : "l"(a), "l"(b));
}

__device__ __forceinline__ u32 smem_u32(const void* p) {
    u32 a;
    asm("{ .reg .u64 t; cvta.to.shared.u64 t, %1; cvt.u32.u64 %0, t; }" : "=r"(a) : "l"(p));
    return a;
}

// bf16 split: 2 floats -> hi bf16x2 + lo bf16x2
__device__ __forceinline__ void split2(float x, float y, u32& h, u32& l) {
    __nv_bfloat162 hb = __float22bfloat162_rn(make_float2(x, y));
    float2 back = __bfloat1622float2(hb);
    __nv_bfloat162 lb = __float22bfloat162_rn(make_float2(x - back.x, y - back.y));
    h = *(u32*)&hb;
    l = *(u32*)&lb;
}

// bf16 split helpers: s[8] floats -> hi uint4 (8 bf16) + lo uint4
__device__ __forceinline__ void split8(const float* s, uint4& h, uint4& l) {
    u32 hh[4], ll[4];
#pragma unroll
    for (int p = 0; p < 4; p++) split2(s[2 * p], s[2 * p + 1], hh[p], ll[p]);
    h = make_uint4(hh[0], hh[1], hh[2], hh[3]);
    l = make_uint4(ll[0], ll[1], ll[2], ll[3]);
}

// mma.sync m16n8k16 bf16
__device__ __forceinline__ void mma_bf16(float* d, const u32* a, const u32* b) {
    asm volatile(
        "mma.sync.aligned.m16n8k16.row.col.f32.bf16.bf16.f32 "
        "{%0,%1,%2,%3}, {%4,%5,%6,%7}, {%8,%9}, {%0,%1,%2,%3};"
        : "+f"(d[0]), "+f"(d[1]), "+f"(d[2]), "+f"(d[3])
        : "r"(a[0]), "r"(a[1]), "r"(a[2]), "r"(a[3]), "r"(b[0]), "r"(b[1]));
}

__device__ __forceinline__ void ldsm_x4(u32* r, u32 addr) {
    asm volatile("ldmatrix.sync.aligned.m8n8.x4.shared.b16 {%0,%1,%2,%3}, [%4];"
        : "=r"(r[0]), "=r"(r[1]), "=r"(r[2]), "=r"(r[3]) : "r"(addr));
}
__device__ __forceinline__ void ldsm_x2(u32* r, u32 addr) {
    asm volatile("ldmatrix.sync.aligned.m8n8.x2.shared.b16 {%0,%1}, [%2];"
        : "=r"(r[0]), "=r"(r[1]) : "r"(addr));
}

#define CP_ASYNC(dst, src) \
    asm volatile("cp.async.cg.shared.global [%0], [%1], 16;" :: "r"(dst), "l"(src) : "memory")
#define CP_COMMIT() asm volatile("cp.async.commit_group;" ::: "memory")
#define CP_WAIT(N)  asm volatile("cp.async.wait_group %0;" :: "n"(N) : "memory")

// ---------- device scratch ----------
__device__ float g_sT[(size_t)F_ * B_];            // stat^T sanitized (4 MB)
__device__ __nv_bfloat16 g_Zh[(size_t)B_ * ZK_];
__device__ __nv_bfloat16 g_Zl[(size_t)B_ * ZK_];
__device__ __nv_bfloat16 g_Bth[(size_t)OUT_ * ZK_];
__device__ __nv_bfloat16 g_Btl[(size_t)OUT_ * ZK_];
__device__ float g_CP[(size_t)SPLITK * B_ * OUT_];

// ============================================================
// Kernel TZ (fused):
//  blocks 0..1023:  sanitize + transpose stat -> g_sT
//  blocks 1024..1919: copy [asr|mm] -> Zh/Zl cols 0..895 (bf16 split)
// ============================================================
__global__ __launch_bounds__(256) void kernelTZ(
    const float* __restrict__ stat,
    const float* __restrict__ asr, const float* __restrict__ mmv)
{
    __shared__ float tile[32][33];
    const int blk = blockIdx.x;
    const int tid = threadIdx.x;
    if (blk < 1024) {
        const int tx = tid & 31, ty = tid >> 5;
        const int f0 = (blk & 15) * 32, b0 = (blk >> 4) * 32;
#pragma unroll
        for (int i = 0; i < 4; i++) {
            float v = stat[(size_t)(b0 + ty + i * 8) * F_ + f0 + tx];
            tile[ty + i * 8][tx] = (v >= 0.f) ? v : 0.f;   // NaN & neg -> 0
        }
        __syncthreads();
#pragma unroll
        for (int i = 0; i < 4; i++)
            g_sT[(size_t)(f0 + ty + i * 8) * B_ + b0 + tx] = tile[tx][ty + i * 8];
    } else {
        const int e = (blk - 1024) * 256 + tid;     // 229376 total
        const int b = e / 112, j8 = e % 112;
        const int col = j8 * 8;
        float s[8];
        if (col < ASR_) {
            const float4* p = (const float4*)(asr + (size_t)b * ASR_ + col);
            float4 v0 = p[0], v1 = p[1];
            s[0]=v0.x; s[1]=v0.y; s[2]=v0.z; s[3]=v0.w;
            s[4]=v1.x; s[5]=v1.y; s[6]=v1.z; s[7]=v1.w;
        } else {
            const float4* p = (const float4*)(mmv + (size_t)b * MM_ + col - ASR_);
            float4 v0 = p[0], v1 = p[1];
            s[0]=v0.x; s[1]=v0.y; s[2]=v0.z; s[3]=v0.w;
            s[4]=v1.x; s[5]=v1.y; s[6]=v1.z; s[7]=v1.w;
        }
        uint4 h, l;
        split8(s, h, l);
        *(uint4*)(g_Zh + (size_t)b * ZK_ + col) = h;
        *(uint4*)(g_Zl + (size_t)b * ZK_ + col) = l;
    }
}

// ============================================================
// Kernel A: per-feature MLP + softmax -> Zh/Zl col 896+f*8
// ============================================================
__global__ __launch_bounds__(256) void kernelA(
    const float* __restrict__ w1, const float* __restrict__ b1,
    const float* __restrict__ w2, const float* __restrict__ b2,
    const float* __restrict__ tau)
{
    __shared__ float w1s[H_], b1s[H_], b2s[K_], taus[K_];
    __shared__ ull   w2s[H_ * K_ / 2];

    const int f = blockIdx.x;
    const int tid = threadIdx.x;

    if (tid < H_) {
        const float* p = w1 + (size_t)f * 3 * H_;
        w1s[tid] = p[tid] + p[H_ + tid] + p[2 * H_ + tid];
        b1s[tid] = b1[(size_t)f * H_ + tid];
    } else if (tid < H_ + K_) {
        b2s[tid - H_] = b2[(size_t)f * K_ + tid - H_];
        taus[tid - H_] = tau[(size_t)f * K_ + tid - H_];
    }
    if (tid < 128) ((float4*)w2s)[tid] = ((const float4*)(w2 + (size_t)f * H_ * K_))[tid];
    __syncthreads();

    float x[8];
#pragma unroll
    for (int i = 0; i < 8; i++)
        x[i] = g_sT[(size_t)f * B_ + i * 256 + tid];

    ull acc[8][4];
#pragma unroll
    for (int i = 0; i < 8; i++)
#pragma unroll
        for (int k = 0; k < 4; k++) acc[i][k] = 0ull;

#pragma unroll 4
    for (int j = 0; j < H_; j++) {
        const float wj = w1s[j];
        const float bj = b1s[j];
        const ull u0 = w2s[j * 4 + 0];
        const ull u1 = w2s[j * 4 + 1];
        const ull u2 = w2s[j * 4 + 2];
        const ull u3 = w2s[j * 4 + 3];
#pragma unroll
        for (int i = 0; i < 8; i++) {
            float h = fmaf(x[i], wj, bj);
            h = fmaxf(h, 0.01f * h);
            ull h2 = pack2(h, h);
            ffma2(acc[i][0], h2, u0);
            ffma2(acc[i][1], h2, u1);
            ffma2(acc[i][2], h2, u2);
            ffma2(acc[i][3], h2, u3);
        }
    }

#pragma unroll
    for (int i = 0; i < 8; i++) {
        float s[8];
#pragma unroll
        for (int k = 0; k < 4; k++) unpack2(acc[i][k], s[2 * k], s[2 * k + 1]);
        float mx = -3.0e38f;
#pragma unroll
        for (int k = 0; k < K_; k++) {
            float pre = s[k] + b2s[k];
            pre = fmaxf(pre, 0.01f * pre);
            pre *= taus[k];
            s[k] = pre;
            mx = fmaxf(mx, pre);
        }
        float sum = 0.f;
#pragma unroll
        for (int k = 0; k < K_; k++) { s[k] = __expf(s[k] - mx); sum += s[k]; }
        const float inv = __frcp_rn(sum);
#pragma unroll
        for (int k = 0; k < K_; k++) s[k] *= inv;
        uint4 h, l;
        split8(s, h, l);
        const size_t off = (size_t)(i * 256 + tid) * ZK_ + ZPRE_ + f * K_;
        *(uint4*)(g_Zh + off) = h;
        *(uint4*)(g_Zl + off) = l;
    }
}

// ============================================================
// Kernel B (mma version): build Bt[256][4992] bf16 hi/lo.
// ============================================================
__global__ __launch_bounds__(256) void kernelB(
    const float* __restrict__ emb, const float* __restrict__ pw)
{
    const int blk = blockIdx.x;
    const int tid = threadIdx.x;
    if (blk < F_) {
        __shared__ float es[K_][D_];   // 4 KB raw emb for this f
        const int f = blk;
        ((float4*)es)[tid] = ((const float4*)(emb + (size_t)f * K_ * D_))[tid];
        __syncthreads();

        const int lane = tid & 31;
        const int w = tid >> 5;
        const int g = lane >> 2;      // 0..7
        const int tg = lane & 3;      // 0..3
        const int o0 = w * 32;        // 32 o-rows per warp

        u32 bh[8][2], bl[8][2];
#pragma unroll
        for (int c = 0; c < 8; c++) {
            const float* er = &es[g][c * 16];
            split2(er[2 * tg],     er[2 * tg + 1], bh[c][0], bl[c][0]);
            split2(er[2 * tg + 8], er[2 * tg + 9], bh[c][1], bl[c][1]);
        }

        float d0[4] = {0.f, 0.f, 0.f, 0.f};
        float d1[4] = {0.f, 0.f, 0.f, 0.f};

        const float* pwb = pw + ZPRE_ + (size_t)f * D_;
#pragma unroll
        for (int c = 0; c < 8; c++) {
            const int dc = c * 16;
#pragma unroll
            for (int mt = 0; mt < 2; mt++) {
                const float* r0 = pwb + (size_t)(o0 + mt * 16 + g) * PROJ_IN_ + dc + 2 * tg;
                const float* r1 = r0 + 8 * PROJ_IN_;
                float2 f0 = *(const float2*)(r0);
                float2 f1 = *(const float2*)(r1);
                float2 f2 = *(const float2*)(r0 + 8);
                float2 f3 = *(const float2*)(r1 + 8);
                u32 ah[4], al[4];
                split2(f0.x, f0.y, ah[0], al[0]);
                split2(f1.x, f1.y, ah[1], al[1]);
                split2(f2.x, f2.y, ah[2], al[2]);
                split2(f3.x, f3.y, ah[3], al[3]);
                float* dd = mt ? d1 : d0;
                mma_bf16(dd, ah, bh[c]);
                mma_bf16(dd, ah, bl[c]);
                mma_bf16(dd, al, bh[c]);
            }
        }

        const size_t cb = ZPRE_ + (size_t)f * K_ + 2 * tg;
#pragma unroll
        for (int mt = 0; mt < 2; mt++) {
            const float* dd = mt ? d1 : d0;
            const int ra = o0 + mt * 16 + g;
            u32 h0, l0, h1, l1;
            split2(dd[0], dd[1], h0, l0);
            split2(dd[2], dd[3], h1, l1);
            *(u32*)(g_Bth + (size_t)ra * ZK_ + cb)       = h0;
            *(u32*)(g_Btl + (size_t)ra * ZK_ + cb)       = l0;
            *(u32*)(g_Bth + (size_t)(ra + 8) * ZK_ + cb) = h1;
            *(u32*)(g_Btl + (size_t)(ra + 8) * ZK_ + cb) = l1;
        }
    } else {
        const int e = (blk - F_) * 256 + tid;
        const int o = e / 112, j8 = e % 112;
        const int col = j8 * 8;
        const float4* p = (const float4*)(pw + (size_t)o * PROJ_IN_ + col);
        float4 v0 = p[0], v1 = p[1];
        float s[8] = {v0.x, v0.y, v0.z, v0.w, v1.x, v1.y, v1.z, v1.w};
        uint4 h, l;
        split8(s, h, l);
        *(uint4*)(g_Bth + (size_t)o * ZK_ + col) = h;
        *(uint4*)(g_Btl + (size_t)o * ZK_ + col) = l;
    }
}

// ============================================================
// Kernel C: mma.sync bf16 split-2 GEMM, cross-iteration software
// pipelining: fragments for iter t+1 loaded before MMAs of iter t.
// BM=128 BN=64 BK=16, warp tile 32x32 (4m x 2n warps), splitK=4.
// grid (16, 4, 4) = 256 CTAs = exactly 1 wave.
// ============================================================
#define ROWB 48
#define A_MATB (128 * ROWB)            // 6144
#define B_MATB (64 * ROWB)             // 3072
#define STAGEB (2 * A_MATB + 2 * B_MATB) // 18432: [Ah|Al|Bh|Bl]
#define NSTAGE 4
#define SMEM_C_BYTES (NSTAGE * STAGEB) // 73728

__global__ __launch_bounds__(256, 2) void kernelC()
{
    extern __shared__ char smem[];
    const u32 smem_base = smem_u32(smem);
    const int tid = threadIdx.x;
    const int gm = blockIdx.x * 128;
    const int gn = blockIdx.y * 64;
    const int kbase = blockIdx.z * KSPLIT;

    const int lane = tid & 31;
    const int w = tid >> 5;
    const int g = lane >> 2;
    const int tg = lane & 3;
    const int m_off = (w & 3) * 32;
    const int n_off = (w >> 2) * 32;

    u32 aoff[2], boff[4];
#pragma unroll
    for (int i = 0; i < 2; i++)
        aoff[i] = (u32)((m_off + i * 16 + (lane & 15)) * ROWB + ((lane >> 4) << 4));
#pragma unroll
    for (int j = 0; j < 4; j++)
        boff[j] = (u32)((n_off + j * 8 + (lane & 7)) * ROWB + (((lane >> 3) & 1) << 4));

    float d[2][4][4];
#pragma unroll
    for (int i = 0; i < 2; i++)
#pragma unroll
        for (int j = 0; j < 4; j++)
#pragma unroll
            for (int c = 0; c < 4; c++) d[i][j][c] = 0.f;

    // double-buffered fragments (cross-iteration pipelining)
    u32 ah[2][2][4], al[2][2][4], bh[2][4][2], bl[2][4][2];

    // cp.async mapping: 768 16B-chunks / 256 threads = 3 each.
    // c<256: Ah, c<512: Al, c<640: Bh, else Bl. row=idx>>1, half=idx&1.
#define FETCH(T, S)                                                                   \
    do {                                                                              \
        const int koff = kbase + (T) * 16;                                            \
        const u32 sb0 = smem_base + (S) * STAGEB;                                     \
        _Pragma("unroll")                                                             \
        for (int ci = 0; ci < 3; ci++) {                                              \
            int c = tid + ci * 256;                                                   \
            const __nv_bfloat16* src;                                                 \
            u32 dst;                                                                  \
            if (c < 512) {                                                            \
                int idx = c & 255, row = idx >> 1, half = idx & 1;                    \
                src = (c < 256 ? g_Zh : g_Zl) + (size_t)(gm + row) * ZK_ + koff + half * 8; \
                dst = sb0 + (c < 256 ? 0 : A_MATB) + row * ROWB + half * 16;          \
            } else {                                                                  \
                int c2 = c - 512, idx = c2 & 127, row = idx >> 1, half = idx & 1;     \
                src = (c2 < 128 ? g_Bth : g_Btl) + (size_t)(gn + row) * ZK_ + koff + half * 8; \
                dst = sb0 + 2 * A_MATB + (c2 < 128 ? 0 : B_MATB) + row * ROWB + half * 16; \
            }                                                                         \
            CP_ASYNC(dst, src);                                                       \
        }                                                                             \
    } while (0)

#define LOADFRAG(BUF, S)                                                              \
    do {                                                                              \
        const u32 sb0 = smem_base + (S) * STAGEB;                                     \
        _Pragma("unroll")                                                             \
        for (int i = 0; i < 2; i++) {                                                 \
            ldsm_x4(ah[BUF][i], sb0 + aoff[i]);                                       \
            ldsm_x4(al[BUF][i], sb0 + A_MATB + aoff[i]);                              \
        }                                                                             \
        _Pragma("unroll")                                                             \
        for (int j = 0; j < 4; j++) {                                                 \
            ldsm_x2(bh[BUF][j], sb0 + 2 * A_MATB + boff[j]);                          \
            ldsm_x2(bl[BUF][j], sb0 + 2 * A_MATB + B_MATB + boff[j]);                 \
        }                                                                             \
    } while (0)

    FETCH(0, 0); CP_COMMIT();
    FETCH(1, 1); CP_COMMIT();
    FETCH(2, 2); CP_COMMIT();
    CP_WAIT(2);
    __syncthreads();
    LOADFRAG(0, 0);

#pragma unroll 1
    for (int t = 0; t < ITERS; t++) {
        // keep the fetch pipe full (empty commit keeps group numbering uniform)
        if (t + 3 < ITERS) FETCH(t + 3, (t + 3) & 3);
        CP_COMMIT();
        CP_WAIT(2);              // stage t+1 now resident
        __syncthreads();

        // prefetch fragments for NEXT iteration — overlaps with MMAs below
        if (t + 1 < ITERS) LOADFRAG((t + 1) & 1, (t + 1) & 3);

        const int b = t & 1;
#pragma unroll
        for (int i = 0; i < 2; i++)
#pragma unroll
            for (int j = 0; j < 4; j++) mma_bf16(d[i][j], ah[b][i], bh[b][j]);  // hi*hi
#pragma unroll
        for (int i = 0; i < 2; i++)
#pragma unroll
            for (int j = 0; j < 4; j++) mma_bf16(d[i][j], ah[b][i], bl[b][j]);  // hi*lo
#pragma unroll
        for (int i = 0; i < 2; i++)
#pragma unroll
            for (int j = 0; j < 4; j++) mma_bf16(d[i][j], al[b][i], bh[b][j]);  // lo*hi
    }

    float* outp = g_CP + (size_t)blockIdx.z * (B_ * OUT_);
#pragma unroll
    for (int i = 0; i < 2; i++) {
        const int row = gm + m_off + 16 * i + g;
#pragma unroll
        for (int j = 0; j < 4; j++) {
            const int col = gn + n_off + 8 * j + 2 * tg;
            *(float2*)(outp + (size_t)row * OUT_ + col)       = make_float2(d[i][j][0], d[i][j][1]);
            *(float2*)(outp + (size_t)(row + 8) * OUT_ + col) = make_float2(d[i][j][2], d[i][j][3]);
        }
    }
#undef FETCH
#undef LOADFRAG
}

// ============================================================
// Kernel D: out = relu(sum_z CP[z] + bias)
// ============================================================
__global__ __launch_bounds__(256) void kernelD(
    const float* __restrict__ pb, float* __restrict__ out)
{
    const int idx = blockIdx.x * 256 + threadIdx.x;
    float4 a = make_float4(0.f, 0.f, 0.f, 0.f);
#pragma unroll
    for (int z = 0; z < SPLITK; z++) {
        float4 v = ((const float4*)g_CP)[(size_t)z * (B_ * OUT_ / 4) + idx];
        a.x += v.x; a.y += v.y; a.z += v.z; a.w += v.w;
    }
    float4 bi = ((const float4*)pb)[idx & (OUT_ / 4 - 1)];
    float4 r;
    r.x = fmaxf(a.x + bi.x, 0.f);
    r.y = fmaxf(a.y + bi.y, 0.f);
    r.z = fmaxf(a.z + bi.z, 0.f);
    r.w = fmaxf(a.w + bi.w, 0.f);
    ((float4*)out)[idx] = r;
}

extern "C" void kernel_launch(void* const* d_in, const int* in_sizes, int n_in,
                              void* d_out, int out_size)
{
    const float* stat = (const float*)d_in[0];
    const float* asr  = (const float*)d_in[1];
    const float* mmv  = (const float*)d_in[2];
    const float* w1   = (const float*)d_in[3];
    const float* b1   = (const float*)d_in[4];
    const float* w2   = (const float*)d_in[5];
    const float* b2   = (const float*)d_in[6];
    const float* tau  = (const float*)d_in[7];
    const float* emb  = (const float*)d_in[8];
    const float* pw   = (const float*)d_in[9];
    const float* pb   = (const float*)d_in[10];
    float* out = (float*)d_out;

    static int smem_set = 0;
    if (!smem_set) {
        cudaFuncSetAttribute(kernelC, cudaFuncAttributeMaxDynamicSharedMemorySize, SMEM_C_BYTES);
        smem_set = 1;
    }

    kernelTZ<<<1024 + 896, 256>>>(stat, asr, mmv);      // idx 0
    kernelA<<<F_, 256>>>(w1, b1, w2, b2, tau);          // idx 1
    kernelB<<<F_ + 112, 256>>>(emb, pw);                // idx 2
    dim3 gc(B_ / 128, OUT_ / 64, SPLITK);
    kernelC<<<gc, 256, SMEM_C_BYTES>>>();               // idx 3  <- profiled
    kernelD<<<(B_ * OUT_ / 4) / 256, 256>>>(pb, out);   // idx 4
}

// round 9
// speedup vs baseline: 2.1194x; 2.1194x over previous
#include <cuda_runtime.h>
#include <cuda_bf16.h>
#include <cuda_fp16.h>
#include <cstdint>

// Problem constants
#define B_    2048
#define F_    512
#define H_    64
#define K_    8
#define D_    128
#define ASR_  128
#define MM_   768
#define OUT_  256
#define ZPRE_ (ASR_ + MM_)          // 896
#define ZK_   (ZPRE_ + F_ * K_)     // 4992
#define PROJ_IN_ (ASR_ + MM_ + F_ * D_)   // 66432
#define SPLITK 8
#define KSPLIT (ZK_ / SPLITK)       // 624
#define ITERS  (KSPLIT / 16)        // 39

typedef unsigned long long ull;
typedef uint32_t u32;

// ---------- packed f32x2 helpers ----------
__device__ __forceinline__ ull pack2(float lo, float hi) {
    ull r; asm("mov.b64 %0, {%1, %2};" : "=l"(r) : "f"(lo), "f"(hi)); return r;
}
__device__ __forceinline__ void unpack2(ull v, float& lo, float& hi) {
    asm("mov.b64 {%0, %1}, %2;" : "=f"(lo), "=f"(hi) : "l"(v));
}
__device__ __forceinline__ void ffma2(ull& c, ull a, ull b) {
    asm("fma.rn.f32x2 %0, %1, %2, %0;" : "+l"(c) : "l"(a), "l"(b));
}

__device__ __forceinline__ u32 smem_u32(const void* p) {
    u32 a;
    asm("{ .reg .u64 t; cvta.to.shared.u64 t, %1; cvt.u32.u64 %0, t; }" : "=r"(a) : "l"(p));
    return a;
}

// fp16 split: 2 floats -> hi half2 + lo half2
__device__ __forceinline__ void split2h(float x, float y, u32& h, u32& l) {
    __half2 hb = __floats2half2_rn(x, y);
    float2 back = __half22float2(hb);
    __half2 lb = __floats2half2_rn(x - back.x, y - back.y);
    h = *(u32*)&hb;
    l = *(u32*)&lb;
}

// 8 floats -> 8 fp16 (hi only, residual dropped)
__device__ __forceinline__ uint4 pack8h(const float* s) {
    __half2 h0 = __floats2half2_rn(s[0], s[1]);
    __half2 h1 = __floats2half2_rn(s[2], s[3]);
    __half2 h2 = __floats2half2_rn(s[4], s[5]);
    __half2 h3 = __floats2half2_rn(s[6], s[7]);
    return make_uint4(*(u32*)&h0, *(u32*)&h1, *(u32*)&h2, *(u32*)&h3);
}

// 8 floats -> fp16 hi uint4 + lo uint4
__device__ __forceinline__ void split8h(const float* s, uint4& h, uint4& l) {
    u32 hh[4], ll[4];
#pragma unroll
    for (int p = 0; p < 4; p++) split2h(s[2 * p], s[2 * p + 1], hh[p], ll[p]);
    h = make_uint4(hh[0], hh[1], hh[2], hh[3]);
    l = make_uint4(ll[0], ll[1], ll[2], ll[3]);
}

// mma.sync m16n8k16 fp16 -> fp32
__device__ __forceinline__ void mma_fp16(float* d, const u32* a, const u32* b) {
    asm volatile(
        "mma.sync.aligned.m16n8k16.row.col.f32.f16.f16.f32 "
        "{%0,%1,%2,%3}, {%4,%5,%6,%7}, {%8,%9}, {%0,%1,%2,%3};"
        : "+f"(d[0]), "+f"(d[1]), "+f"(d[2]), "+f"(d[3])
        : "r"(a[0]), "r"(a[1]), "r"(a[2]), "r"(a[3]), "r"(b[0]), "r"(b[1]));
}

__device__ __forceinline__ void ldsm_x4(u32* r, u32 addr) {
    asm volatile("ldmatrix.sync.aligned.m8n8.x4.shared.b16 {%0,%1,%2,%3}, [%4];"
        : "=r"(r[0]), "=r"(r[1]), "=r"(r[2]), "=r"(r[3]) : "r"(addr));
}
__device__ __forceinline__ void ldsm_x2(u32* r, u32 addr) {
    asm volatile("ldmatrix.sync.aligned.m8n8.x2.shared.b16 {%0,%1}, [%2];"
        : "=r"(r[0]), "=r"(r[1]) : "r"(addr));
}

#define CP_ASYNC(dst, src) \
    asm volatile("cp.async.cg.shared.global [%0], [%1], 16;" :: "r"(dst), "l"(src) : "memory")
#define CP_COMMIT() asm volatile("cp.async.commit_group;" ::: "memory")
#define CP_WAIT(N)  asm volatile("cp.async.wait_group %0;" :: "n"(N) : "memory")

// ---------- device scratch ----------
__device__ float g_sT[(size_t)F_ * B_];            // stat^T sanitized (4 MB)
__device__ __half g_Zh[(size_t)B_ * ZK_];          // 20 MB (A operand, hi only)
__device__ __half g_Bth[(size_t)OUT_ * ZK_];       // 2.5 MB
__device__ __half g_Btl[(size_t)OUT_ * ZK_];       // 2.5 MB
__device__ float g_CP[(size_t)SPLITK * B_ * OUT_];

// ============================================================
// Kernel TZ (fused):
//  blocks 0..1023:  sanitize + transpose stat -> g_sT
//  blocks 1024..1919: [asr|mm] -> Zh cols 0..895 (fp16)
// ============================================================
__global__ __launch_bounds__(256) void kernelTZ(
    const float* __restrict__ stat,
    const float* __restrict__ asr, const float* __restrict__ mmv)
{
    __shared__ float tile[32][33];
    const int blk = blockIdx.x;
    const int tid = threadIdx.x;
    if (blk < 1024) {
        const int tx = tid & 31, ty = tid >> 5;
        const int f0 = (blk & 15) * 32, b0 = (blk >> 4) * 32;
#pragma unroll
        for (int i = 0; i < 4; i++) {
            float v = stat[(size_t)(b0 + ty + i * 8) * F_ + f0 + tx];
            tile[ty + i * 8][tx] = (v >= 0.f) ? v : 0.f;   // NaN & neg -> 0
        }
        __syncthreads();
#pragma unroll
        for (int i = 0; i < 4; i++)
            g_sT[(size_t)(f0 + ty + i * 8) * B_ + b0 + tx] = tile[tx][ty + i * 8];
    } else {
        const int e = (blk - 1024) * 256 + tid;     // 229376 total
        const int b = e / 112, j8 = e % 112;
        const int col = j8 * 8;
        float s[8];
        if (col < ASR_) {
            const float4* p = (const float4*)(asr + (size_t)b * ASR_ + col);
            float4 v0 = p[0], v1 = p[1];
            s[0]=v0.x; s[1]=v0.y; s[2]=v0.z; s[3]=v0.w;
            s[4]=v1.x; s[5]=v1.y; s[6]=v1.z; s[7]=v1.w;
        } else {
            const float4* p = (const float4*)(mmv + (size_t)b * MM_ + col - ASR_);
            float4 v0 = p[0], v1 = p[1];
            s[0]=v0.x; s[1]=v0.y; s[2]=v0.z; s[3]=v0.w;
            s[4]=v1.x; s[5]=v1.y; s[6]=v1.z; s[7]=v1.w;
        }
        *(uint4*)(g_Zh + (size_t)b * ZK_ + col) = pack8h(s);
    }
}

// ============================================================
// Kernel A: per-feature MLP + softmax -> Zh col 896+f*8 (fp16)
// ============================================================
__global__ __launch_bounds__(256) void kernelA(
    const float* __restrict__ w1, const float* __restrict__ b1,
    const float* __restrict__ w2, const float* __restrict__ b2,
    const float* __restrict__ tau)
{
    __shared__ float w1s[H_], b1s[H_], b2s[K_], taus[K_];
    __shared__ ull   w2s[H_ * K_ / 2];

    const int f = blockIdx.x;
    const int tid = threadIdx.x;

    if (tid < H_) {
        const float* p = w1 + (size_t)f * 3 * H_;
        w1s[tid] = p[tid] + p[H_ + tid] + p[2 * H_ + tid];
        b1s[tid] = b1[(size_t)f * H_ + tid];
    } else if (tid < H_ + K_) {
        b2s[tid - H_] = b2[(size_t)f * K_ + tid - H_];
        taus[tid - H_] = tau[(size_t)f * K_ + tid - H_];
    }
    if (tid < 128) ((float4*)w2s)[tid] = ((const float4*)(w2 + (size_t)f * H_ * K_))[tid];
    __syncthreads();

    float x[8];
#pragma unroll
    for (int i = 0; i < 8; i++)
        x[i] = g_sT[(size_t)f * B_ + i * 256 + tid];

    ull acc[8][4];
#pragma unroll
    for (int i = 0; i < 8; i++)
#pragma unroll
        for (int k = 0; k < 4; k++) acc[i][k] = 0ull;

#pragma unroll 4
    for (int j = 0; j < H_; j++) {
        const float wj = w1s[j];
        const float bj = b1s[j];
        const ull u0 = w2s[j * 4 + 0];
        const ull u1 = w2s[j * 4 + 1];
        const ull u2 = w2s[j * 4 + 2];
        const ull u3 = w2s[j * 4 + 3];
#pragma unroll
        for (int i = 0; i < 8; i++) {
            float h = fmaf(x[i], wj, bj);
            h = fmaxf(h, 0.01f * h);
            ull h2 = pack2(h, h);
            ffma2(acc[i][0], h2, u0);
            ffma2(acc[i][1], h2, u1);
            ffma2(acc[i][2], h2, u2);
            ffma2(acc[i][3], h2, u3);
        }
    }

#pragma unroll
    for (int i = 0; i < 8; i++) {
        float s[8];
#pragma unroll
        for (int k = 0; k < 4; k++) unpack2(acc[i][k], s[2 * k], s[2 * k + 1]);
        float mx = -3.0e38f;
#pragma unroll
        for (int k = 0; k < K_; k++) {
            float pre = s[k] + b2s[k];
            pre = fmaxf(pre, 0.01f * pre);
            pre *= taus[k];
            s[k] = pre;
            mx = fmaxf(mx, pre);
        }
        float sum = 0.f;
#pragma unroll
        for (int k = 0; k < K_; k++) { s[k] = __expf(s[k] - mx); sum += s[k]; }
        const float inv = __frcp_rn(sum);
#pragma unroll
        for (int k = 0; k < K_; k++) s[k] *= inv;
        const size_t off = (size_t)(i * 256 + tid) * ZK_ + ZPRE_ + f * K_;
        *(uint4*)(g_Zh + off) = pack8h(s);
    }
}

// ============================================================
// Kernel B: build Bt[256][4992] fp16 hi/lo.
// M-build per f via fp16 split-2 3-term MMA (accuracy ~2^-22).
// ============================================================
__global__ __launch_bounds__(256) void kernelB(
    const float* __restrict__ emb, const float* __restrict__ pw)
{
    const int blk = blockIdx.x;
    const int tid = threadIdx.x;
    if (blk < F_) {
        __shared__ float es[K_][D_];   // 4 KB raw emb for this f
        const int f = blk;
        ((float4*)es)[tid] = ((const float4*)(emb + (size_t)f * K_ * D_))[tid];
        __syncthreads();

        const int lane = tid & 31;
        const int w = tid >> 5;
        const int g = lane >> 2;      // 0..7
        const int tg = lane & 3;      // 0..3
        const int o0 = w * 32;        // 32 o-rows per warp

        u32 bh[8][2], bl[8][2];
#pragma unroll
        for (int c = 0; c < 8; c++) {
            const float* er = &es[g][c * 16];
            split2h(er[2 * tg],     er[2 * tg + 1], bh[c][0], bl[c][0]);
            split2h(er[2 * tg + 8], er[2 * tg + 9], bh[c][1], bl[c][1]);
        }

        float d0[4] = {0.f, 0.f, 0.f, 0.f};
        float d1[4] = {0.f, 0.f, 0.f, 0.f};

        const float* pwb = pw + ZPRE_ + (size_t)f * D_;
#pragma unroll
        for (int c = 0; c < 8; c++) {
            const int dc = c * 16;
#pragma unroll
            for (int mt = 0; mt < 2; mt++) {
                const float* r0 = pwb + (size_t)(o0 + mt * 16 + g) * PROJ_IN_ + dc + 2 * tg;
                const float* r1 = r0 + 8 * PROJ_IN_;
                float2 f0 = *(const float2*)(r0);
                float2 f1 = *(const float2*)(r1);
                float2 f2 = *(const float2*)(r0 + 8);
                float2 f3 = *(const float2*)(r1 + 8);
                u32 ah[4], al[4];
                split2h(f0.x, f0.y, ah[0], al[0]);
                split2h(f1.x, f1.y, ah[1], al[1]);
                split2h(f2.x, f2.y, ah[2], al[2]);
                split2h(f3.x, f3.y, ah[3], al[3]);
                float* dd = mt ? d1 : d0;
                mma_fp16(dd, ah, bh[c]);
                mma_fp16(dd, ah, bl[c]);
                mma_fp16(dd, al, bh[c]);
            }
        }

        const size_t cb = ZPRE_ + (size_t)f * K_ + 2 * tg;
#pragma unroll
        for (int mt = 0; mt < 2; mt++) {
            const float* dd = mt ? d1 : d0;
            const int ra = o0 + mt * 16 + g;
            u32 h0, l0, h1, l1;
            split2h(dd[0], dd[1], h0, l0);
            split2h(dd[2], dd[3], h1, l1);
            *(u32*)(g_Bth + (size_t)ra * ZK_ + cb)       = h0;
            *(u32*)(g_Btl + (size_t)ra * ZK_ + cb)       = l0;
            *(u32*)(g_Bth + (size_t)(ra + 8) * ZK_ + cb) = h1;
            *(u32*)(g_Btl + (size_t)(ra + 8) * ZK_ + cb) = l1;
        }
    } else {
        const int e = (blk - F_) * 256 + tid;
        const int o = e / 112, j8 = e % 112;
        const int col = j8 * 8;
        const float4* p = (const float4*)(pw + (size_t)o * PROJ_IN_ + col);
        float4 v0 = p[0], v1 = p[1];
        float s[8] = {v0.x, v0.y, v0.z, v0.w, v1.x, v1.y, v1.z, v1.w};
        uint4 h, l;
        split8h(s, h, l);
        *(uint4*)(g_Bth + (size_t)o * ZK_ + col) = h;
        *(uint4*)(g_Btl + (size_t)o * ZK_ + col) = l;
    }
}

// ============================================================
// Kernel C: mma.sync fp16 2-term GEMM (C = Zh*Bh + Zh*Bl).
// BM=128 BN=128 BK=16, splitK=8 -> grid (16, 2, 8) = 256 CTAs.
// 4-stage cp.async, single-buffered fragments (no reg spills).
// ============================================================
#define ROWB 48
#define MATB (128 * ROWB)              // 6144
#define STAGEB (3 * MATB)              // 18432: [A | Bh | Bl]
#define NSTAGE 4
#define SMEM_C_BYTES (NSTAGE * STAGEB) // 73728

__global__ __launch_bounds__(256, 2) void kernelC()
{
    extern __shared__ char smem[];
    const u32 smem_base = smem_u32(smem);
    const int tid = threadIdx.x;
    const int gm = blockIdx.x * 128;
    const int gn = blockIdx.y * 128;
    const int kbase = blockIdx.z * KSPLIT;

    const int lane = tid & 31;
    const int w = tid >> 5;
    const int g = lane >> 2;
    const int tg = lane & 3;
    const int m_off = (w & 3) * 32;
    const int n_off = (w >> 2) * 64;

    u32 aoff[2], boff[8];
#pragma unroll
    for (int i = 0; i < 2; i++)
        aoff[i] = (u32)((m_off + i * 16 + (lane & 15)) * ROWB + ((lane >> 4) << 4));
#pragma unroll
    for (int j = 0; j < 8; j++)
        boff[j] = (u32)((n_off + j * 8 + (lane & 7)) * ROWB + (((lane >> 3) & 1) << 4));

    float d[2][8][4];
#pragma unroll
    for (int i = 0; i < 2; i++)
#pragma unroll
        for (int j = 0; j < 8; j++)
#pragma unroll
            for (int c = 0; c < 4; c++) d[i][j][c] = 0.f;

    // cp.async: 768 16B-chunks / 256 threads = 3 each
    // c<256: A(Zh), c<512: Bh, c<768: Bl. row=idx>>1, half=idx&1.
#define FETCH(T, S)                                                                  \
    do {                                                                             \
        const int koff = kbase + (T) * 16;                                           \
        const u32 sb0 = smem_base + (S) * STAGEB;                                    \
        _Pragma("unroll")                                                            \
        for (int ci = 0; ci < 3; ci++) {                                             \
            int c = tid + ci * 256;                                                  \
            int mat = c >> 8, idx = c & 255, row = idx >> 1, half = idx & 1;         \
            const __half* src;                                                       \
            if (mat == 0)      src = g_Zh  + (size_t)(gm + row) * ZK_ + koff + half * 8; \
            else if (mat == 1) src = g_Bth + (size_t)(gn + row) * ZK_ + koff + half * 8; \
            else               src = g_Btl + (size_t)(gn + row) * ZK_ + koff + half * 8; \
            u32 dst = sb0 + mat * MATB + row * ROWB + half * 16;                     \
            CP_ASYNC(dst, src);                                                      \
        }                                                                            \
    } while (0)

    FETCH(0, 0); CP_COMMIT();
    FETCH(1, 1); CP_COMMIT();
    FETCH(2, 2); CP_COMMIT();

#pragma unroll 1
    for (int t = 0; t < ITERS; t++) {
        CP_WAIT(2);
        __syncthreads();

        if (t + 3 < ITERS) FETCH(t + 3, (t + 3) & 3);
        CP_COMMIT();

        const u32 sb = smem_base + (t & 3) * STAGEB;

        u32 ah[2][4], bh[8][2], bl[8][2];
#pragma unroll
        for (int i = 0; i < 2; i++) ldsm_x4(ah[i], sb + aoff[i]);
#pragma unroll
        for (int j = 0; j < 8; j++) ldsm_x2(bh[j], sb + MATB + boff[j]);
#pragma unroll
        for (int j = 0; j < 8; j++) ldsm_x2(bl[j], sb + 2 * MATB + boff[j]);

#pragma unroll
        for (int i = 0; i < 2; i++)
#pragma unroll
            for (int j = 0; j < 8; j++) mma_fp16(d[i][j], ah[i], bh[j]);   // Zh*Bh
#pragma unroll
        for (int i = 0; i < 2; i++)
#pragma unroll
            for (int j = 0; j < 8; j++) mma_fp16(d[i][j], ah[i], bl[j]);   // Zh*Bl
    }

    float* outp = g_CP + (size_t)blockIdx.z * (B_ * OUT_);
#pragma unroll
    for (int i = 0; i < 2; i++) {
        const int row = gm + m_off + 16 * i + g;
#pragma unroll
        for (int j = 0; j < 8; j++) {
            const int col = gn + n_off + 8 * j + 2 * tg;
            *(float2*)(outp + (size_t)row * OUT_ + col)       = make_float2(d[i][j][0], d[i][j][1]);
            *(float2*)(outp + (size_t)(row + 8) * OUT_ + col) = make_float2(d[i][j][2], d[i][j][3]);
        }
    }
#undef FETCH
}

// ============================================================
// Kernel D: out = relu(sum_z CP[z] + bias)
// ============================================================
__global__ __launch_bounds__(256) void kernelD(
    const float* __restrict__ pb, float* __restrict__ out)
{
    const int idx = blockIdx.x * 256 + threadIdx.x;
    float4 a = make_float4(0.f, 0.f, 0.f, 0.f);
#pragma unroll
    for (int z = 0; z < SPLITK; z++) {
        float4 v = ((const float4*)g_CP)[(size_t)z * (B_ * OUT_ / 4) + idx];
        a.x += v.x; a.y += v.y; a.z += v.z; a.w += v.w;
    }
    float4 bi = ((const float4*)pb)[idx & (OUT_ / 4 - 1)];
    float4 r;
    r.x = fmaxf(a.x + bi.x, 0.f);
    r.y = fmaxf(a.y + bi.y, 0.f);
    r.z = fmaxf(a.z + bi.z, 0.f);
    r.w = fmaxf(a.w + bi.w, 0.f);
    ((float4*)out)[idx] = r;
}

extern "C" void kernel_launch(void* const* d_in, const int* in_sizes, int n_in,
                              void* d_out, int out_size)
{
    const float* stat = (const float*)d_in[0];
    const float* asr  = (const float*)d_in[1];
    const float* mmv  = (const float*)d_in[2];
    const float* w1   = (const float*)d_in[3];
    const float* b1   = (const float*)d_in[4];
    const float* w2   = (const float*)d_in[5];
    const float* b2   = (const float*)d_in[6];
    const float* tau  = (const float*)d_in[7];
    const float* emb  = (const float*)d_in[8];
    const float* pw   = (const float*)d_in[9];
    const float* pb   = (const float*)d_in[10];
    float* out = (float*)d_out;

    static int smem_set = 0;
    if (!smem_set) {
        cudaFuncSetAttribute(kernelC, cudaFuncAttributeMaxDynamicSharedMemorySize, SMEM_C_BYTES);
        smem_set = 1;
    }

    kernelTZ<<<1024 + 896, 256>>>(stat, asr, mmv);      // idx 0
    kernelA<<<F_, 256>>>(w1, b1, w2, b2, tau);          // idx 1
    kernelB<<<F_ + 112, 256>>>(emb, pw);                // idx 2
    dim3 gc(B_ / 128, OUT_ / 128, SPLITK);
    kernelC<<<gc, 256, SMEM_C_BYTES>>>();               // idx 3  <- profiled
    kernelD<<<(B_ * OUT_ / 4) / 256, 256>>>(pb, out);   // idx 4
}

// round 10
// speedup vs baseline: 2.5999x; 1.2267x over previous
#include <cuda_runtime.h>
#include <cuda_bf16.h>
#include <cuda_fp16.h>
#include <cstdint>

// Problem constants
#define B_    2048
#define F_    512
#define H_    64
#define K_    8
#define D_    128
#define ASR_  128
#define MM_   768
#define OUT_  256
#define ZPRE_ (ASR_ + MM_)          // 896
#define ZK_   (ZPRE_ + F_ * K_)     // 4992 (real contraction dim)
#define ZKP_  5120                  // padded to mult of 256 (pad cols are zero)
#define PROJ_IN_ (ASR_ + MM_ + F_ * D_)   // 66432
#define SPLITK 8
#define KSPLIT (ZKP_ / SPLITK)      // 640
#define BK    32
#define ITERS (KSPLIT / BK)         // 20

typedef unsigned long long ull;
typedef uint32_t u32;

// ---------- packed f32x2 helpers ----------
__device__ __forceinline__ ull pack2(float lo, float hi) {
    ull r; asm("mov.b64 %0, {%1, %2};" : "=l"(r) : "f"(lo), "f"(hi)); return r;
}
__device__ __forceinline__ void unpack2(ull v, float& lo, float& hi) {
    asm("mov.b64 {%0, %1}, %2;" : "=f"(lo), "=f"(hi) : "l"(v));
}
__device__ __forceinline__ void ffma2(ull& c, ull a, ull b) {
    asm("fma.rn.f32x2 %0, %1, %2, %0;" : "+l"(c) : "l"(a), "l"(b));
}

__device__ __forceinline__ u32 smem_u32(const void* p) {
    u32 a;
    asm("{ .reg .u64 t; cvta.to.shared.u64 t, %1; cvt.u32.u64 %0, t; }" : "=r"(a) : "l"(p));
    return a;
}

// fp16 split: 2 floats -> hi half2 + lo half2
__device__ __forceinline__ void split2h(float x, float y, u32& h, u32& l) {
    __half2 hb = __floats2half2_rn(x, y);
    float2 back = __half22float2(hb);
    __half2 lb = __floats2half2_rn(x - back.x, y - back.y);
    h = *(u32*)&hb;
    l = *(u32*)&lb;
}

// 8 floats -> 8 fp16 (rounded, residual dropped)
__device__ __forceinline__ uint4 pack8h(const float* s) {
    __half2 h0 = __floats2half2_rn(s[0], s[1]);
    __half2 h1 = __floats2half2_rn(s[2], s[3]);
    __half2 h2 = __floats2half2_rn(s[4], s[5]);
    __half2 h3 = __floats2half2_rn(s[6], s[7]);
    return make_uint4(*(u32*)&h0, *(u32*)&h1, *(u32*)&h2, *(u32*)&h3);
}

// mma.sync m16n8k16 fp16 -> fp32
__device__ __forceinline__ void mma_fp16(float* d, const u32* a, const u32* b) {
    asm volatile(
        "mma.sync.aligned.m16n8k16.row.col.f32.f16.f16.f32 "
        "{%0,%1,%2,%3}, {%4,%5,%6,%7}, {%8,%9}, {%0,%1,%2,%3};"
        : "+f"(d[0]), "+f"(d[1]), "+f"(d[2]), "+f"(d[3])
        : "r"(a[0]), "r"(a[1]), "r"(a[2]), "r"(a[3]), "r"(b[0]), "r"(b[1]));
}

__device__ __forceinline__ void ldsm_x4(u32* r, u32 addr) {
    asm volatile("ldmatrix.sync.aligned.m8n8.x4.shared.b16 {%0,%1,%2,%3}, [%4];"
        : "=r"(r[0]), "=r"(r[1]), "=r"(r[2]), "=r"(r[3]) : "r"(addr));
}
__device__ __forceinline__ void ldsm_x2(u32* r, u32 addr) {
    asm volatile("ldmatrix.sync.aligned.m8n8.x2.shared.b16 {%0,%1}, [%2];"
        : "=r"(r[0]), "=r"(r[1]) : "r"(addr));
}

#define CP_ASYNC(dst, src) \
    asm volatile("cp.async.cg.shared.global [%0], [%1], 16;" :: "r"(dst), "l"(src) : "memory")
#define CP_COMMIT() asm volatile("cp.async.commit_group;" ::: "memory")
#define CP_WAIT(N)  asm volatile("cp.async.wait_group %0;" :: "n"(N) : "memory")

// ---------- device scratch (zero-initialized; pad cols never written) ----------
__device__ float g_sT[(size_t)F_ * B_];            // stat^T sanitized (4 MB)
__device__ __half g_Zh[(size_t)B_ * ZKP_];         // 21 MB (A operand, fp16)
__device__ __half g_Bth[(size_t)OUT_ * ZKP_];      // 2.6 MB (B operand, fp16)
__device__ float g_CP[(size_t)SPLITK * B_ * OUT_];

// ============================================================
// Kernel TZ (fused):
//  blocks 0..1023:  sanitize + transpose stat -> g_sT
//  blocks 1024..1919: [asr|mm] -> Zh cols 0..895 (fp16)
// ============================================================
__global__ __launch_bounds__(256) void kernelTZ(
    const float* __restrict__ stat,
    const float* __restrict__ asr, const float* __restrict__ mmv)
{
    __shared__ float tile[32][33];
    const int blk = blockIdx.x;
    const int tid = threadIdx.x;
    if (blk < 1024) {
        const int tx = tid & 31, ty = tid >> 5;
        const int f0 = (blk & 15) * 32, b0 = (blk >> 4) * 32;
#pragma unroll
        for (int i = 0; i < 4; i++) {
            float v = stat[(size_t)(b0 + ty + i * 8) * F_ + f0 + tx];
            tile[ty + i * 8][tx] = (v >= 0.f) ? v : 0.f;   // NaN & neg -> 0
        }
        __syncthreads();
#pragma unroll
        for (int i = 0; i < 4; i++)
            g_sT[(size_t)(f0 + ty + i * 8) * B_ + b0 + tx] = tile[tx][ty + i * 8];
    } else {
        const int e = (blk - 1024) * 256 + tid;     // 229376 total
        const int b = e / 112, j8 = e % 112;
        const int col = j8 * 8;
        float s[8];
        if (col < ASR_) {
            const float4* p = (const float4*)(asr + (size_t)b * ASR_ + col);
            float4 v0 = p[0], v1 = p[1];
            s[0]=v0.x; s[1]=v0.y; s[2]=v0.z; s[3]=v0.w;
            s[4]=v1.x; s[5]=v1.y; s[6]=v1.z; s[7]=v1.w;
        } else {
            const float4* p = (const float4*)(mmv + (size_t)b * MM_ + col - ASR_);
            float4 v0 = p[0], v1 = p[1];
            s[0]=v0.x; s[1]=v0.y; s[2]=v0.z; s[3]=v0.w;
            s[4]=v1.x; s[5]=v1.y; s[6]=v1.z; s[7]=v1.w;
        }
        *(uint4*)(g_Zh + (size_t)b * ZKP_ + col) = pack8h(s);
    }
}

// ============================================================
// Kernel A: per-feature MLP + softmax -> Zh col 896+f*8 (fp16)
// ============================================================
__global__ __launch_bounds__(256) void kernelA(
    const float* __restrict__ w1, const float* __restrict__ b1,
    const float* __restrict__ w2, const float* __restrict__ b2,
    const float* __restrict__ tau)
{
    __shared__ float w1s[H_], b1s[H_], b2s[K_], taus[K_];
    __shared__ ull   w2s[H_ * K_ / 2];

    const int f = blockIdx.x;
    const int tid = threadIdx.x;

    if (tid < H_) {
        const float* p = w1 + (size_t)f * 3 * H_;
        w1s[tid] = p[tid] + p[H_ + tid] + p[2 * H_ + tid];
        b1s[tid] = b1[(size_t)f * H_ + tid];
    } else if (tid < H_ + K_) {
        b2s[tid - H_] = b2[(size_t)f * K_ + tid - H_];
        taus[tid - H_] = tau[(size_t)f * K_ + tid - H_];
    }
    if (tid < 128) ((float4*)w2s)[tid] = ((const float4*)(w2 + (size_t)f * H_ * K_))[tid];
    __syncthreads();

    float x[8];
#pragma unroll
    for (int i = 0; i < 8; i++)
        x[i] = g_sT[(size_t)f * B_ + i * 256 + tid];

    ull acc[8][4];
#pragma unroll
    for (int i = 0; i < 8; i++)
#pragma unroll
        for (int k = 0; k < 4; k++) acc[i][k] = 0ull;

#pragma unroll 4
    for (int j = 0; j < H_; j++) {
        const float wj = w1s[j];
        const float bj = b1s[j];
        const ull u0 = w2s[j * 4 + 0];
        const ull u1 = w2s[j * 4 + 1];
        const ull u2 = w2s[j * 4 + 2];
        const ull u3 = w2s[j * 4 + 3];
#pragma unroll
        for (int i = 0; i < 8; i++) {
            float h = fmaf(x[i], wj, bj);
            h = fmaxf(h, 0.01f * h);
            ull h2 = pack2(h, h);
            ffma2(acc[i][0], h2, u0);
            ffma2(acc[i][1], h2, u1);
            ffma2(acc[i][2], h2, u2);
            ffma2(acc[i][3], h2, u3);
        }
    }

#pragma unroll
    for (int i = 0; i < 8; i++) {
        float s[8];
#pragma unroll
        for (int k = 0; k < 4; k++) unpack2(acc[i][k], s[2 * k], s[2 * k + 1]);
        float mx = -3.0e38f;
#pragma unroll
        for (int k = 0; k < K_; k++) {
            float pre = s[k] + b2s[k];
            pre = fmaxf(pre, 0.01f * pre);
            pre *= taus[k];
            s[k] = pre;
            mx = fmaxf(mx, pre);
        }
        float sum = 0.f;
#pragma unroll
        for (int k = 0; k < K_; k++) { s[k] = __expf(s[k] - mx); sum += s[k]; }
        const float inv = __frcp_rn(sum);
#pragma unroll
        for (int k = 0; k < K_; k++) s[k] *= inv;
        const size_t off = (size_t)(i * 256 + tid) * ZKP_ + ZPRE_ + f * K_;
        *(uint4*)(g_Zh + off) = pack8h(s);
    }
}

// ============================================================
// Kernel B: build Bt[256][ZKP] fp16 (hi only).
// M-build per f via fp16 split-2 3-term MMA (M computed to ~2^-22,
// then stored as fp16 — same quantization as other columns).
// ============================================================
__global__ __launch_bounds__(256) void kernelB(
    const float* __restrict__ emb, const float* __restrict__ pw)
{
    const int blk = blockIdx.x;
    const int tid = threadIdx.x;
    if (blk < F_) {
        __shared__ float es[K_][D_];   // 4 KB raw emb for this f
        const int f = blk;
        ((float4*)es)[tid] = ((const float4*)(emb + (size_t)f * K_ * D_))[tid];
        __syncthreads();

        const int lane = tid & 31;
        const int w = tid >> 5;
        const int g = lane >> 2;      // 0..7
        const int tg = lane & 3;      // 0..3
        const int o0 = w * 32;        // 32 o-rows per warp

        u32 bh[8][2], bl[8][2];
#pragma unroll
        for (int c = 0; c < 8; c++) {
            const float* er = &es[g][c * 16];
            split2h(er[2 * tg],     er[2 * tg + 1], bh[c][0], bl[c][0]);
            split2h(er[2 * tg + 8], er[2 * tg + 9], bh[c][1], bl[c][1]);
        }

        float d0[4] = {0.f, 0.f, 0.f, 0.f};
        float d1[4] = {0.f, 0.f, 0.f, 0.f};

        const float* pwb = pw + ZPRE_ + (size_t)f * D_;
#pragma unroll
        for (int c = 0; c < 8; c++) {
            const int dc = c * 16;
#pragma unroll
            for (int mt = 0; mt < 2; mt++) {
                const float* r0 = pwb + (size_t)(o0 + mt * 16 + g) * PROJ_IN_ + dc + 2 * tg;
                const float* r1 = r0 + 8 * PROJ_IN_;
                float2 f0 = *(const float2*)(r0);
                float2 f1 = *(const float2*)(r1);
                float2 f2 = *(const float2*)(r0 + 8);
                float2 f3 = *(const float2*)(r1 + 8);
                u32 ah[4], al[4];
                split2h(f0.x, f0.y, ah[0], al[0]);
                split2h(f1.x, f1.y, ah[1], al[1]);
                split2h(f2.x, f2.y, ah[2], al[2]);
                split2h(f3.x, f3.y, ah[3], al[3]);
                float* dd = mt ? d1 : d0;
                mma_fp16(dd, ah, bh[c]);
                mma_fp16(dd, ah, bl[c]);
                mma_fp16(dd, al, bh[c]);
            }
        }

        const size_t cb = ZPRE_ + (size_t)f * K_ + 2 * tg;
#pragma unroll
        for (int mt = 0; mt < 2; mt++) {
            const float* dd = mt ? d1 : d0;
            const int ra = o0 + mt * 16 + g;
            __half2 h0 = __floats2half2_rn(dd[0], dd[1]);
            __half2 h1 = __floats2half2_rn(dd[2], dd[3]);
            *(u32*)(g_Bth + (size_t)ra * ZKP_ + cb)       = *(u32*)&h0;
            *(u32*)(g_Bth + (size_t)(ra + 8) * ZKP_ + cb) = *(u32*)&h1;
        }
    } else {
        const int e = (blk - F_) * 256 + tid;
        const int o = e / 112, j8 = e % 112;
        const int col = j8 * 8;
        const float4* p = (const float4*)(pw + (size_t)o * PROJ_IN_ + col);
        float4 v0 = p[0], v1 = p[1];
        float s[8] = {v0.x, v0.y, v0.z, v0.w, v1.x, v1.y, v1.z, v1.w};
        *(uint4*)(g_Bth + (size_t)o * ZKP_ + col) = pack8h(s);
    }
}

// ============================================================
// Kernel C: single-term fp16 mma.sync GEMM (C = Zh*Bh).
// BM=128 BN=128 BK=32, splitK=8 -> grid (16, 2, 8) = 256 CTAs.
// 4-stage cp.async, 32 MMAs + 20 ldmatrix per iteration.
// ============================================================
#define ROWB 80                        // 64B data + 16B pad (conflict-free ldsm)
#define MATB (128 * ROWB)              // 10240
#define STAGEB (2 * MATB)              // 20480: [A | B]
#define NSTAGE 4
#define SMEM_C_BYTES (NSTAGE * STAGEB) // 81920

__global__ __launch_bounds__(256, 2) void kernelC()
{
    extern __shared__ char smem[];
    const u32 smem_base = smem_u32(smem);
    const int tid = threadIdx.x;
    const int gm = blockIdx.x * 128;
    const int gn = blockIdx.y * 128;
    const int kbase = blockIdx.z * KSPLIT;

    const int lane = tid & 31;
    const int w = tid >> 5;
    const int g = lane >> 2;
    const int tg = lane & 3;
    const int m_off = (w & 3) * 32;
    const int n_off = (w >> 2) * 64;

    u32 aoff[2], boff[8];
#pragma unroll
    for (int i = 0; i < 2; i++)
        aoff[i] = (u32)((m_off + i * 16 + (lane & 15)) * ROWB + ((lane >> 4) << 4));
#pragma unroll
    for (int j = 0; j < 8; j++)
        boff[j] = (u32)((n_off + j * 8 + (lane & 7)) * ROWB + (((lane >> 3) & 1) << 4));

    float d[2][8][4];
#pragma unroll
    for (int i = 0; i < 2; i++)
#pragma unroll
        for (int j = 0; j < 8; j++)
#pragma unroll
            for (int c = 0; c < 4; c++) d[i][j][c] = 0.f;

    // cp.async: 1024 16B-chunks / 256 threads = 4 each.
    // c<512: A rows (4 chunks/row), else B rows. row=idx>>2, q=idx&3.
#define FETCH(T, S)                                                                  \
    do {                                                                             \
        const int koff = kbase + (T) * BK;                                           \
        const u32 sb0 = smem_base + (S) * STAGEB;                                    \
        _Pragma("unroll")                                                            \
        for (int ci = 0; ci < 4; ci++) {                                             \
            int c = tid + ci * 256;                                                  \
            int idx = c & 511, row = idx >> 2, q = idx & 3;                          \
            const __half* src;                                                       \
            u32 dst;                                                                 \
            if (c < 512) {                                                           \
                src = g_Zh + (size_t)(gm + row) * ZKP_ + koff + q * 8;               \
                dst = sb0 + row * ROWB + q * 16;                                     \
            } else {                                                                 \
                src = g_Bth + (size_t)(gn + row) * ZKP_ + koff + q * 8;              \
                dst = sb0 + MATB + row * ROWB + q * 16;                              \
            }                                                                        \
            CP_ASYNC(dst, src);                                                      \
        }                                                                            \
    } while (0)

    FETCH(0, 0); CP_COMMIT();
    FETCH(1, 1); CP_COMMIT();
    FETCH(2, 2); CP_COMMIT();

#pragma unroll 1
    for (int t = 0; t < ITERS; t++) {
        CP_WAIT(2);
        __syncthreads();

        if (t + 3 < ITERS) FETCH(t + 3, (t + 3) & 3);
        CP_COMMIT();

        const u32 sb = smem_base + (t & 3) * STAGEB;

        // both 16-k slices' fragments up front (48 frag regs + 64 acc)
        u32 ah[2][2][4], bh[2][8][2];
#pragma unroll
        for (int s = 0; s < 2; s++) {
            const u32 kb = s * 32;
#pragma unroll
            for (int i = 0; i < 2; i++) ldsm_x4(ah[s][i], sb + aoff[i] + kb);
#pragma unroll
            for (int j = 0; j < 8; j++) ldsm_x2(bh[s][j], sb + MATB + boff[j] + kb);
        }
#pragma unroll
        for (int s = 0; s < 2; s++)
#pragma unroll
            for (int i = 0; i < 2; i++)
#pragma unroll
                for (int j = 0; j < 8; j++) mma_fp16(d[i][j], ah[s][i], bh[s][j]);
    }

    float* outp = g_CP + (size_t)blockIdx.z * (B_ * OUT_);
#pragma unroll
    for (int i = 0; i < 2; i++) {
        const int row = gm + m_off + 16 * i + g;
#pragma unroll
        for (int j = 0; j < 8; j++) {
            const int col = gn + n_off + 8 * j + 2 * tg;
            *(float2*)(outp + (size_t)row * OUT_ + col)       = make_float2(d[i][j][0], d[i][j][1]);
            *(float2*)(outp + (size_t)(row + 8) * OUT_ + col) = make_float2(d[i][j][2], d[i][j][3]);
        }
    }
#undef FETCH
}

// ============================================================
// Kernel D: out = relu(sum_z CP[z] + bias)
// ============================================================
__global__ __launch_bounds__(256) void kernelD(
    const float* __restrict__ pb, float* __restrict__ out)
{
    const int idx = blockIdx.x * 256 + threadIdx.x;
    float4 a = make_float4(0.f, 0.f, 0.f, 0.f);
#pragma unroll
    for (int z = 0; z < SPLITK; z++) {
        float4 v = ((const float4*)g_CP)[(size_t)z * (B_ * OUT_ / 4) + idx];
        a.x += v.x; a.y += v.y; a.z += v.z; a.w += v.w;
    }
    float4 bi = ((const float4*)pb)[idx & (OUT_ / 4 - 1)];
    float4 r;
    r.x = fmaxf(a.x + bi.x, 0.f);
    r.y = fmaxf(a.y + bi.y, 0.f);
    r.z = fmaxf(a.z + bi.z, 0.f);
    r.w = fmaxf(a.w + bi.w, 0.f);
    ((float4*)out)[idx] = r;
}

extern "C" void kernel_launch(void* const* d_in, const int* in_sizes, int n_in,
                              void* d_out, int out_size)
{
    const float* stat = (const float*)d_in[0];
    const float* asr  = (const float*)d_in[1];
    const float* mmv  = (const float*)d_in[2];
    const float* w1   = (const float*)d_in[3];
    const float* b1   = (const float*)d_in[4];
    const float* w2   = (const float*)d_in[5];
    const float* b2   = (const float*)d_in[6];
    const float* tau  = (const float*)d_in[7];
    const float* emb  = (const float*)d_in[8];
    const float* pw   = (const float*)d_in[9];
    const float* pb   = (const float*)d_in[10];
    float* out = (float*)d_out;

    static int smem_set = 0;
    if (!smem_set) {
        cudaFuncSetAttribute(kernelC, cudaFuncAttributeMaxDynamicSharedMemorySize, SMEM_C_BYTES);
        smem_set = 1;
    }

    kernelTZ<<<1024 + 896, 256>>>(stat, asr, mmv);      // idx 0
    kernelA<<<F_, 256>>>(w1, b1, w2, b2, tau);          // idx 1
    kernelB<<<F_ + 112, 256>>>(emb, pw);                // idx 2
    dim3 gc(B_ / 128, OUT_ / 128, SPLITK);
    kernelC<<<gc, 256, SMEM_C_BYTES>>>();               // idx 3  <- profiled
    kernelD<<<(B_ * OUT_ / 4) / 256, 256>>>(pb, out);   // idx 4
}

// round 11
// speedup vs baseline: 2.6644x; 1.0248x over previous
#include <cuda_runtime.h>
#include <cuda_bf16.h>
#include <cuda_fp16.h>
#include <cstdint>

// Problem constants
#define B_    2048
#define F_    512
#define H_    64
#define K_    8
#define D_    128
#define ASR_  128
#define MM_   768
#define OUT_  256
#define ZPRE_ (ASR_ + MM_)          // 896
#define ZK_   (ZPRE_ + F_ * K_)     // 4992 (real contraction dim)
#define ZKP_  5120                  // padded (pad cols stay zero)
#define PROJ_IN_ (ASR_ + MM_ + F_ * D_)   // 66432
#define SPLITK 8
#define KSPLIT (ZKP_ / SPLITK)      // 640
#define BK    32
#define ITERS (KSPLIT / BK)         // 20

typedef unsigned long long ull;
typedef uint32_t u32;

// ---------- packed f32x2 helpers ----------
__device__ __forceinline__ ull pack2(float lo, float hi) {
    ull r; asm("mov.b64 %0, {%1, %2};" : "=l"(r) : "f"(lo), "f"(hi)); return r;
}
__device__ __forceinline__ void unpack2(ull v, float& lo, float& hi) {
    asm("mov.b64 {%0, %1}, %2;" : "=f"(lo), "=f"(hi) : "l"(v));
}
__device__ __forceinline__ void ffma2(ull& c, ull a, ull b) {
    asm("fma.rn.f32x2 %0, %1, %2, %0;" : "+l"(c) : "l"(a), "l"(b));
}

__device__ __forceinline__ u32 smem_u32(const void* p) {
    u32 a;
    asm("{ .reg .u64 t; cvta.to.shared.u64 t, %1; cvt.u32.u64 %0, t; }" : "=r"(a) : "l"(p));
    return a;
}

// fp16 split: 2 floats -> hi half2 + lo half2
__device__ __forceinline__ void split2h(float x, float y, u32& h, u32& l) {
    __half2 hb = __floats2half2_rn(x, y);
    float2 back = __half22float2(hb);
    __half2 lb = __floats2half2_rn(x - back.x, y - back.y);
    h = *(u32*)&hb;
    l = *(u32*)&lb;
}

// 8 floats -> 8 fp16
__device__ __forceinline__ uint4 pack8h(const float* s) {
    __half2 h0 = __floats2half2_rn(s[0], s[1]);
    __half2 h1 = __floats2half2_rn(s[2], s[3]);
    __half2 h2 = __floats2half2_rn(s[4], s[5]);
    __half2 h3 = __floats2half2_rn(s[6], s[7]);
    return make_uint4(*(u32*)&h0, *(u32*)&h1, *(u32*)&h2, *(u32*)&h3);
}

// mma.sync m16n8k16 fp16 -> fp32
__device__ __forceinline__ void mma_fp16(float* d, const u32* a, const u32* b) {
    asm volatile(
        "mma.sync.aligned.m16n8k16.row.col.f32.f16.f16.f32 "
        "{%0,%1,%2,%3}, {%4,%5,%6,%7}, {%8,%9}, {%0,%1,%2,%3};"
        : "+f"(d[0]), "+f"(d[1]), "+f"(d[2]), "+f"(d[3])
        : "r"(a[0]), "r"(a[1]), "r"(a[2]), "r"(a[3]), "r"(b[0]), "r"(b[1]));
}

__device__ __forceinline__ void ldsm_x4(u32* r, u32 addr) {
    asm volatile("ldmatrix.sync.aligned.m8n8.x4.shared.b16 {%0,%1,%2,%3}, [%4];"
        : "=r"(r[0]), "=r"(r[1]), "=r"(r[2]), "=r"(r[3]) : "r"(addr));
}
__device__ __forceinline__ void ldsm_x2(u32* r, u32 addr) {
    asm volatile("ldmatrix.sync.aligned.m8n8.x2.shared.b16 {%0,%1}, [%2];"
        : "=r"(r[0]), "=r"(r[1]) : "r"(addr));
}

#define CP_ASYNC(dst, src) \
    asm volatile("cp.async.cg.shared.global [%0], [%1], 16;" :: "r"(dst), "l"(src) : "memory")
#define CP_COMMIT() asm volatile("cp.async.commit_group;" ::: "memory")
#define CP_WAIT(N)  asm volatile("cp.async.wait_group %0;" :: "n"(N) : "memory")

// ---------- device scratch (zero-initialized; pad cols never written) ----------
__device__ float g_sT[(size_t)F_ * B_];            // stat^T sanitized (4 MB)
__device__ __half g_Zh[(size_t)B_ * ZKP_];         // 21 MB (A operand, fp16)
__device__ __half g_Bth[(size_t)OUT_ * ZKP_];      // 2.6 MB (B operand, fp16)
__device__ float g_CP[(size_t)SPLITK * B_ * OUT_];

// ============================================================
// Kernel T: sanitize + transpose stat[2048][512] -> g_sT[512][2048]
// ============================================================
__global__ __launch_bounds__(256) void kernelT(const float* __restrict__ stat)
{
    __shared__ float tile[32][33];
    const int tid = threadIdx.x;
    const int tx = tid & 31, ty = tid >> 5;
    const int f0 = (blockIdx.x & 15) * 32, b0 = (blockIdx.x >> 4) * 32;
#pragma unroll
    for (int i = 0; i < 4; i++) {
        float v = stat[(size_t)(b0 + ty + i * 8) * F_ + f0 + tx];
        tile[ty + i * 8][tx] = (v >= 0.f) ? v : 0.f;   // NaN & neg -> 0
    }
    __syncthreads();
#pragma unroll
    for (int i = 0; i < 4; i++)
        g_sT[(size_t)(f0 + ty + i * 8) * B_ + b0 + tx] = tile[tx][ty + i * 8];
}

// ============================================================
// Kernel Z: [asr|mm] -> Zh cols 0..895 (fp16). 896 blocks.
// ============================================================
__global__ __launch_bounds__(256) void kernelZ(
    const float* __restrict__ asr, const float* __restrict__ mmv)
{
    const int e = blockIdx.x * 256 + threadIdx.x;     // 229376 total
    const int b = e / 112, j8 = e % 112;
    const int col = j8 * 8;
    float s[8];
    if (col < ASR_) {
        const float4* p = (const float4*)(asr + (size_t)b * ASR_ + col);
        float4 v0 = p[0], v1 = p[1];
        s[0]=v0.x; s[1]=v0.y; s[2]=v0.z; s[3]=v0.w;
        s[4]=v1.x; s[5]=v1.y; s[6]=v1.z; s[7]=v1.w;
    } else {
        const float4* p = (const float4*)(mmv + (size_t)b * MM_ + col - ASR_);
        float4 v0 = p[0], v1 = p[1];
        s[0]=v0.x; s[1]=v0.y; s[2]=v0.z; s[3]=v0.w;
        s[4]=v1.x; s[5]=v1.y; s[6]=v1.z; s[7]=v1.w;
    }
    *(uint4*)(g_Zh + (size_t)b * ZKP_ + col) = pack8h(s);
}

// ============================================================
// Kernel AB (fused): interleaved A-work and B-work blocks so the
// FMA-bound MLP and the DRAM-bound proj_w stream overlap on-SM.
//   blk < 1024:  even -> A (f = blk>>1), odd -> B M-build (f = blk>>1)
//   blk >= 1024: B copy of proj_w cols 0..895 (112 blocks)
// ============================================================
__global__ __launch_bounds__(256) void kernelAB(
    const float* __restrict__ w1, const float* __restrict__ b1,
    const float* __restrict__ w2, const float* __restrict__ b2,
    const float* __restrict__ tau,
    const float* __restrict__ emb, const float* __restrict__ pw)
{
    const int blk = blockIdx.x;
    const int tid = threadIdx.x;

    if (blk < 1024 && (blk & 1) == 0) {
        // ---------------- A: per-feature MLP + softmax ----------------
        __shared__ float w1s[H_], b1s[H_], b2s[K_], taus[K_];
        __shared__ ull   w2s[H_ * K_ / 2];
        const int f = blk >> 1;

        if (tid < H_) {
            const float* p = w1 + (size_t)f * 3 * H_;
            w1s[tid] = p[tid] + p[H_ + tid] + p[2 * H_ + tid];
            b1s[tid] = b1[(size_t)f * H_ + tid];
        } else if (tid < H_ + K_) {
            b2s[tid - H_] = b2[(size_t)f * K_ + tid - H_];
            taus[tid - H_] = tau[(size_t)f * K_ + tid - H_];
        }
        if (tid < 128) ((float4*)w2s)[tid] = ((const float4*)(w2 + (size_t)f * H_ * K_))[tid];
        __syncthreads();

        float x[8];
#pragma unroll
        for (int i = 0; i < 8; i++)
            x[i] = g_sT[(size_t)f * B_ + i * 256 + tid];

        ull acc[8][4];
#pragma unroll
        for (int i = 0; i < 8; i++)
#pragma unroll
            for (int k = 0; k < 4; k++) acc[i][k] = 0ull;

#pragma unroll 4
        for (int j = 0; j < H_; j++) {
            const float wj = w1s[j];
            const float bj = b1s[j];
            const ull u0 = w2s[j * 4 + 0];
            const ull u1 = w2s[j * 4 + 1];
            const ull u2 = w2s[j * 4 + 2];
            const ull u3 = w2s[j * 4 + 3];
#pragma unroll
            for (int i = 0; i < 8; i++) {
                float h = fmaf(x[i], wj, bj);
                h = fmaxf(h, 0.01f * h);
                ull h2 = pack2(h, h);
                ffma2(acc[i][0], h2, u0);
                ffma2(acc[i][1], h2, u1);
                ffma2(acc[i][2], h2, u2);
                ffma2(acc[i][3], h2, u3);
            }
        }

#pragma unroll
        for (int i = 0; i < 8; i++) {
            float s[8];
#pragma unroll
            for (int k = 0; k < 4; k++) unpack2(acc[i][k], s[2 * k], s[2 * k + 1]);
            float mx = -3.0e38f;
#pragma unroll
            for (int k = 0; k < K_; k++) {
                float pre = s[k] + b2s[k];
                pre = fmaxf(pre, 0.01f * pre);
                pre *= taus[k];
                s[k] = pre;
                mx = fmaxf(mx, pre);
            }
            float sum = 0.f;
#pragma unroll
            for (int k = 0; k < K_; k++) { s[k] = __expf(s[k] - mx); sum += s[k]; }
            const float inv = __frcp_rn(sum);
#pragma unroll
            for (int k = 0; k < K_; k++) s[k] *= inv;
            const size_t off = (size_t)(i * 256 + tid) * ZKP_ + ZPRE_ + f * K_;
            *(uint4*)(g_Zh + off) = pack8h(s);
        }
    } else if (blk < 1024) {
        // ---------------- B: M-build via fp16 split-2 MMA ----------------
        __shared__ float es[K_][D_];   // 4 KB raw emb for this f
        const int f = blk >> 1;
        ((float4*)es)[tid] = ((const float4*)(emb + (size_t)f * K_ * D_))[tid];
        __syncthreads();

        const int lane = tid & 31;
        const int w = tid >> 5;
        const int g = lane >> 2;      // 0..7
        const int tg = lane & 3;      // 0..3
        const int o0 = w * 32;        // 32 o-rows per warp

        u32 bh[8][2], bl[8][2];
#pragma unroll
        for (int c = 0; c < 8; c++) {
            const float* er = &es[g][c * 16];
            split2h(er[2 * tg],     er[2 * tg + 1], bh[c][0], bl[c][0]);
            split2h(er[2 * tg + 8], er[2 * tg + 9], bh[c][1], bl[c][1]);
        }

        float d0[4] = {0.f, 0.f, 0.f, 0.f};
        float d1[4] = {0.f, 0.f, 0.f, 0.f};

        const float* pwb = pw + ZPRE_ + (size_t)f * D_;
#pragma unroll
        for (int c = 0; c < 8; c++) {
            const int dc = c * 16;
#pragma unroll
            for (int mt = 0; mt < 2; mt++) {
                const float* r0 = pwb + (size_t)(o0 + mt * 16 + g) * PROJ_IN_ + dc + 2 * tg;
                const float* r1 = r0 + 8 * PROJ_IN_;
                float2 f0 = *(const float2*)(r0);
                float2 f1 = *(const float2*)(r1);
                float2 f2 = *(const float2*)(r0 + 8);
                float2 f3 = *(const float2*)(r1 + 8);
                u32 ah[4], al[4];
                split2h(f0.x, f0.y, ah[0], al[0]);
                split2h(f1.x, f1.y, ah[1], al[1]);
                split2h(f2.x, f2.y, ah[2], al[2]);
                split2h(f3.x, f3.y, ah[3], al[3]);
                float* dd = mt ? d1 : d0;
                mma_fp16(dd, ah, bh[c]);
                mma_fp16(dd, ah, bl[c]);
                mma_fp16(dd, al, bh[c]);
            }
        }

        const size_t cb = ZPRE_ + (size_t)f * K_ + 2 * tg;
#pragma unroll
        for (int mt = 0; mt < 2; mt++) {
            const float* dd = mt ? d1 : d0;
            const int ra = o0 + mt * 16 + g;
            __half2 h0 = __floats2half2_rn(dd[0], dd[1]);
            __half2 h1 = __floats2half2_rn(dd[2], dd[3]);
            *(u32*)(g_Bth + (size_t)ra * ZKP_ + cb)       = *(u32*)&h0;
            *(u32*)(g_Bth + (size_t)(ra + 8) * ZKP_ + cb) = *(u32*)&h1;
        }
    } else {
        // ---------------- B: copy proj_w cols 0..895 ----------------
        const int e = (blk - 1024) * 256 + tid;
        const int o = e / 112, j8 = e % 112;
        const int col = j8 * 8;
        const float4* p = (const float4*)(pw + (size_t)o * PROJ_IN_ + col);
        float4 v0 = p[0], v1 = p[1];
        float s[8] = {v0.x, v0.y, v0.z, v0.w, v1.x, v1.y, v1.z, v1.w};
        *(uint4*)(g_Bth + (size_t)o * ZKP_ + col) = pack8h(s);
    }
}

// ============================================================
// Kernel C: single-term fp16 mma.sync GEMM (C = Zh*Bh).
// BM=128 BN=128 BK=32, splitK=8 -> grid (16, 2, 8) = 256 CTAs.
// 4-stage cp.async, 32 MMAs + 20 ldmatrix per iteration.
// ============================================================
#define ROWB 80                        // 64B data + 16B pad (conflict-free ldsm)
#define MATB (128 * ROWB)              // 10240
#define STAGEB (2 * MATB)              // 20480: [A | B]
#define NSTAGE 4
#define SMEM_C_BYTES (NSTAGE * STAGEB) // 81920

__global__ __launch_bounds__(256, 2) void kernelC()
{
    extern __shared__ char smem[];
    const u32 smem_base = smem_u32(smem);
    const int tid = threadIdx.x;
    const int gm = blockIdx.x * 128;
    const int gn = blockIdx.y * 128;
    const int kbase = blockIdx.z * KSPLIT;

    const int lane = tid & 31;
    const int w = tid >> 5;
    const int g = lane >> 2;
    const int tg = lane & 3;
    const int m_off = (w & 3) * 32;
    const int n_off = (w >> 2) * 64;

    u32 aoff[2], boff[8];
#pragma unroll
    for (int i = 0; i < 2; i++)
        aoff[i] = (u32)((m_off + i * 16 + (lane & 15)) * ROWB + ((lane >> 4) << 4));
#pragma unroll
    for (int j = 0; j < 8; j++)
        boff[j] = (u32)((n_off + j * 8 + (lane & 7)) * ROWB + (((lane >> 3) & 1) << 4));

    float d[2][8][4];
#pragma unroll
    for (int i = 0; i < 2; i++)
#pragma unroll
        for (int j = 0; j < 8; j++)
#pragma unroll
            for (int c = 0; c < 4; c++) d[i][j][c] = 0.f;

#define FETCH(T, S)                                                                  \
    do {                                                                             \
        const int koff = kbase + (T) * BK;                                           \
        const u32 sb0 = smem_base + (S) * STAGEB;                                    \
        _Pragma("unroll")                                                            \
        for (int ci = 0; ci < 4; ci++) {                                             \
            int c = tid + ci * 256;                                                  \
            int idx = c & 511, row = idx >> 2, q = idx & 3;                          \
            const __half* src;                                                       \
            u32 dst;                                                                 \
            if (c < 512) {                                                           \
                src = g_Zh + (size_t)(gm + row) * ZKP_ + koff + q * 8;               \
                dst = sb0 + row * ROWB + q * 16;                                     \
            } else {                                                                 \
                src = g_Bth + (size_t)(gn + row) * ZKP_ + koff + q * 8;              \
                dst = sb0 + MATB + row * ROWB + q * 16;                              \
            }                                                                        \
            CP_ASYNC(dst, src);                                                      \
        }                                                                            \
    } while (0)

    FETCH(0, 0); CP_COMMIT();
    FETCH(1, 1); CP_COMMIT();
    FETCH(2, 2); CP_COMMIT();

#pragma unroll 1
    for (int t = 0; t < ITERS; t++) {
        CP_WAIT(2);
        __syncthreads();

        if (t + 3 < ITERS) FETCH(t + 3, (t + 3) & 3);
        CP_COMMIT();

        const u32 sb = smem_base + (t & 3) * STAGEB;

        u32 ah[2][2][4], bh[2][8][2];
#pragma unroll
        for (int s = 0; s < 2; s++) {
            const u32 kb = s * 32;
#pragma unroll
            for (int i = 0; i < 2; i++) ldsm_x4(ah[s][i], sb + aoff[i] + kb);
#pragma unroll
            for (int j = 0; j < 8; j++) ldsm_x2(bh[s][j], sb + MATB + boff[j] + kb);
        }
#pragma unroll
        for (int s = 0; s < 2; s++)
#pragma unroll
            for (int i = 0; i < 2; i++)
#pragma unroll
                for (int j = 0; j < 8; j++) mma_fp16(d[i][j], ah[s][i], bh[s][j]);
    }

    float* outp = g_CP + (size_t)blockIdx.z * (B_ * OUT_);
#pragma unroll
    for (int i = 0; i < 2; i++) {
        const int row = gm + m_off + 16 * i + g;
#pragma unroll
        for (int j = 0; j < 8; j++) {
            const int col = gn + n_off + 8 * j + 2 * tg;
            *(float2*)(outp + (size_t)row * OUT_ + col)       = make_float2(d[i][j][0], d[i][j][1]);
            *(float2*)(outp + (size_t)(row + 8) * OUT_ + col) = make_float2(d[i][j][2], d[i][j][3]);
        }
    }
#undef FETCH
}

// ============================================================
// Kernel D: out = relu(sum_z CP[z] + bias)
// ============================================================
__global__ __launch_bounds__(256) void kernelD(
    const float* __restrict__ pb, float* __restrict__ out)
{
    const int idx = blockIdx.x * 256 + threadIdx.x;
    float4 a = make_float4(0.f, 0.f, 0.f, 0.f);
#pragma unroll
    for (int z = 0; z < SPLITK; z++) {
        float4 v = ((const float4*)g_CP)[(size_t)z * (B_ * OUT_ / 4) + idx];
        a.x += v.x; a.y += v.y; a.z += v.z; a.w += v.w;
    }
    float4 bi = ((const float4*)pb)[idx & (OUT_ / 4 - 1)];
    float4 r;
    r.x = fmaxf(a.x + bi.x, 0.f);
    r.y = fmaxf(a.y + bi.y, 0.f);
    r.z = fmaxf(a.z + bi.z, 0.f);
    r.w = fmaxf(a.w + bi.w, 0.f);
    ((float4*)out)[idx] = r;
}

extern "C" void kernel_launch(void* const* d_in, const int* in_sizes, int n_in,
                              void* d_out, int out_size)
{
    const float* stat = (const float*)d_in[0];
    const float* asr  = (const float*)d_in[1];
    const float* mmv  = (const float*)d_in[2];
    const float* w1   = (const float*)d_in[3];
    const float* b1   = (const float*)d_in[4];
    const float* w2   = (const float*)d_in[5];
    const float* b2   = (const float*)d_in[6];
    const float* tau  = (const float*)d_in[7];
    const float* emb  = (const float*)d_in[8];
    const float* pw   = (const float*)d_in[9];
    const float* pb   = (const float*)d_in[10];
    float* out = (float*)d_out;

    static int smem_set = 0;
    if (!smem_set) {
        cudaFuncSetAttribute(kernelC, cudaFuncAttributeMaxDynamicSharedMemorySize, SMEM_C_BYTES);
        smem_set = 1;
    }

    kernelT<<<1024, 256>>>(stat);                             // idx 0
    kernelAB<<<1024 + 112, 256>>>(w1, b1, w2, b2, tau, emb, pw); // idx 1 (A ∥ B)
    kernelZ<<<896, 256>>>(asr, mmv);                          // idx 2
    dim3 gc(B_ / 128, OUT_ / 128, SPLITK);
    kernelC<<<gc, 256, SMEM_C_BYTES>>>();                     // idx 3  <- profiled
    kernelD<<<(B_ * OUT_ / 4) / 256, 256>>>(pb, out);         // idx 4
}